// round 1
// baseline (speedup 1.0000x reference)
#include <cuda_runtime.h>
#include <math.h>

// ---------------------------------------------------------------------------
// MoE top-1 routed FFN, fp32 baseline.
//   x:[8192,1024]  Wr:[16,1024]  wg:[8,16]
//   W1:[8,1024,2048] b1:[8,2048]  W2:[8,2048,1024] b2:[8,1024]
//   out:[8192,1024]
// Pipeline: prep (fold gate weights, zero counters) -> gate (logits/softmax/
// argmax + bucket tokens per expert) -> grouped GEMM1 (gelu) -> grouped GEMM2
// (bias + score scale, scatter to out).
// ---------------------------------------------------------------------------

#define N_TOK 8192
#define C_DIM 1024
#define H_DIM 2048
#define N_EXP 8
#define R_DIM 16

// Scratch (allocation-free: __device__ globals)
__device__ float g_M8[N_EXP * C_DIM];          // folded gate matrix  [8,1024]
__device__ int   g_cnt[N_EXP];                 // tokens per expert
__device__ int   g_perm[N_EXP * N_TOK];        // token ids per expert bucket
__device__ float g_score[N_TOK];               // top-1 gate value per token
__device__ float g_h[(size_t)N_TOK * H_DIM];   // 64MB hidden activations

// ---------------------------------------------------------------------------
// prep: M8[e][c] = sum_j (wg[e][j]/max(||wg[e]||,eps)) * Wr[j][c];  zero cnts
// grid: 32 x 256  (one thread per (e,c))
// ---------------------------------------------------------------------------
__global__ void prep_kernel(const float* __restrict__ Wr,
                            const float* __restrict__ wg) {
    int gid = blockIdx.x * blockDim.x + threadIdx.x;   // 0..8191
    if (gid < N_EXP) g_cnt[gid] = 0;
    int e = gid >> 10;
    int c = gid & (C_DIM - 1);
    float s = 0.f;
#pragma unroll
    for (int j = 0; j < R_DIM; j++) { float v = wg[e * R_DIM + j]; s += v * v; }
    float inv = 1.f / fmaxf(sqrtf(s), 1e-4f);
    float acc = 0.f;
#pragma unroll
    for (int j = 0; j < R_DIM; j++)
        acc += wg[e * R_DIM + j] * inv * Wr[j * C_DIM + c];
    g_M8[e * C_DIM + c] = acc;
}

// ---------------------------------------------------------------------------
// gate: one warp per token. logits[e] = dot(x[t], M8[e]); softmax; top-1.
// grid: N_TOK/8 x 256
// ---------------------------------------------------------------------------
__global__ __launch_bounds__(256) void gate_kernel(const float* __restrict__ x) {
    __shared__ float sM[N_EXP * C_DIM];   // 32 KB
    for (int i = threadIdx.x; i < N_EXP * C_DIM; i += 256) sM[i] = g_M8[i];
    __syncthreads();

    int warp = threadIdx.x >> 5;
    int lane = threadIdx.x & 31;
    int t = blockIdx.x * 8 + warp;
    const float* xr = x + (size_t)t * C_DIM;

    float acc[N_EXP];
#pragma unroll
    for (int e = 0; e < N_EXP; e++) acc[e] = 0.f;

    for (int k0 = 0; k0 < C_DIM; k0 += 32) {
        float xv = xr[k0 + lane];
#pragma unroll
        for (int e = 0; e < N_EXP; e++)
            acc[e] += xv * sM[e * C_DIM + k0 + lane];
    }
#pragma unroll
    for (int e = 0; e < N_EXP; e++) {
#pragma unroll
        for (int off = 16; off > 0; off >>= 1)
            acc[e] += __shfl_xor_sync(0xffffffffu, acc[e], off);
    }
    if (lane == 0) {
        float m = acc[0]; int idx = 0;
#pragma unroll
        for (int e = 1; e < N_EXP; e++)
            if (acc[e] > m) { m = acc[e]; idx = e; }
        float s = 0.f;
#pragma unroll
        for (int e = 0; e < N_EXP; e++) s += expf(acc[e] - m);
        g_score[t] = 1.0f / s;          // softmax value of the max logit
        int pos = atomicAdd(&g_cnt[idx], 1);
        g_perm[idx * N_TOK + pos] = t;
    }
}

// ---------------------------------------------------------------------------
// Grouped GEMM, 128x128x8 tile, 256 threads, 8x8 micro-tile / thread,
// global->reg prefetch software pipeline.
//   GELU=true : A = x (gathered rows), B = W1[e], out = g_h, epilogue gelu
//   GELU=false: A = g_h (gathered),    B = W2[e], out = d_out, *score scatter
// grid: (ND/128, 64, N_EXP)
// ---------------------------------------------------------------------------
template <int KD, int ND, bool GELU>
__global__ __launch_bounds__(256, 2)
void ffn_gemm(const float* __restrict__ A_in,
              const float* __restrict__ W,
              const float* __restrict__ bias,
              float* __restrict__ out_ext) {
    const int e   = blockIdx.z;
    const int cnt = g_cnt[e];
    const int m0  = blockIdx.y * 128;
    if (m0 >= cnt) return;
    const int n0  = blockIdx.x * 128;

    const float* A_base = GELU ? A_in : (const float*)g_h;
    float*       O_base = GELU ? (float*)g_h : out_ext;

    __shared__ float As[8][132];   // padded: conflict-free + 16B-aligned rows
    __shared__ float Bs[8][128];

    const int tid = threadIdx.x;

    // A tile loads: 2 threads per row, one float4 each (row-major K)
    const int arow = tid >> 1, aseg = tid & 1;
    const int am   = m0 + arow;
    const int amc  = am < cnt ? am : cnt - 1;
    const int atok = g_perm[e * N_TOK + amc];
    const float* aptr = A_base + (size_t)atok * KD + aseg * 4;

    // B tile loads: 32 threads per k-row, one float4 each (row-major N)
    const int brow = tid >> 5, bcol = (tid & 31) * 4;
    const float* bptr = W + (size_t)e * KD * ND + (size_t)brow * ND + n0 + bcol;

    const int tx = tid & 15, ty = tid >> 4;

    float acc[8][8];
#pragma unroll
    for (int i = 0; i < 8; i++)
#pragma unroll
        for (int j = 0; j < 8; j++) acc[i][j] = 0.f;

    float4 aReg = *(const float4*)aptr;
    float4 bReg = *(const float4*)bptr;

    const int KT = KD / 8;
#pragma unroll 1
    for (int kt = 0; kt < KT; kt++) {
        As[aseg * 4 + 0][arow] = aReg.x;
        As[aseg * 4 + 1][arow] = aReg.y;
        As[aseg * 4 + 2][arow] = aReg.z;
        As[aseg * 4 + 3][arow] = aReg.w;
        *(float4*)&Bs[brow][bcol] = bReg;
        __syncthreads();

        if (kt + 1 < KT) {
            aReg = *(const float4*)(aptr + (kt + 1) * 8);
            bReg = *(const float4*)(bptr + (size_t)(kt + 1) * 8 * ND);
        }

#pragma unroll
        for (int k = 0; k < 8; k++) {
            float a[8], b[8];
            *(float4*)(a + 0) = *(const float4*)&As[k][ty * 8 + 0];
            *(float4*)(a + 4) = *(const float4*)&As[k][ty * 8 + 4];
            *(float4*)(b + 0) = *(const float4*)&Bs[k][tx * 8 + 0];
            *(float4*)(b + 4) = *(const float4*)&Bs[k][tx * 8 + 4];
#pragma unroll
            for (int i = 0; i < 8; i++)
#pragma unroll
                for (int j = 0; j < 8; j++)
                    acc[i][j] += a[i] * b[j];
        }
        __syncthreads();
    }

    // Epilogue
    const float* brow_bias = bias + (size_t)e * ND + n0 + tx * 8;
#pragma unroll
    for (int i = 0; i < 8; i++) {
        int m = m0 + ty * 8 + i;
        if (m >= cnt) continue;
        int tok = g_perm[e * N_TOK + m];
        float v[8];
        if (GELU) {
#pragma unroll
            for (int j = 0; j < 8; j++) {
                float z = acc[i][j] + brow_bias[j];
                v[j] = 0.5f * z * (1.0f + erff(z * 0.70710678118654752f));
            }
        } else {
            float sc = g_score[tok];
#pragma unroll
            for (int j = 0; j < 8; j++)
                v[j] = (acc[i][j] + brow_bias[j]) * sc;
        }
        float* op = O_base + (size_t)tok * ND + n0 + tx * 8;
        *(float4*)(op + 0) = *(float4*)(v + 0);
        *(float4*)(op + 4) = *(float4*)(v + 4);
    }
}

// ---------------------------------------------------------------------------
extern "C" void kernel_launch(void* const* d_in, const int* in_sizes, int n_in,
                              void* d_out, int out_size) {
    const float* x  = (const float*)d_in[0];
    const float* Wr = (const float*)d_in[1];
    const float* wg = (const float*)d_in[2];
    const float* W1 = (const float*)d_in[3];
    const float* b1 = (const float*)d_in[4];
    const float* W2 = (const float*)d_in[5];
    const float* b2 = (const float*)d_in[6];
    float* out = (float*)d_out;

    prep_kernel<<<(N_EXP * C_DIM) / 256, 256>>>(Wr, wg);
    gate_kernel<<<N_TOK / 8, 256>>>(x);

    dim3 g1(H_DIM / 128, N_TOK / 128, N_EXP);
    ffn_gemm<C_DIM, H_DIM, true><<<g1, 256>>>(x, W1, b1, nullptr);

    dim3 g2(C_DIM / 128, N_TOK / 128, N_EXP);
    ffn_gemm<H_DIM, C_DIM, false><<<g2, 256>>>(nullptr, W2, b2, out);
}

// round 3
// speedup vs baseline: 2.6516x; 2.6516x over previous
#include <cuda_runtime.h>
#include <cuda_bf16.h>
#include <cstdint>
#include <math.h>

// ===========================================================================
// MoE top-1 routed FFN — bf16 split (hi/lo, 3-MMA) via mma.sync (plain sm_100).
//   x:[8192,1024] Wr:[16,1024] wg:[8,16]
//   W1:[8,1024,2048] b1:[8,2048] W2:[8,2048,1024] b2:[8,1024] -> out:[8192,1024]
// ===========================================================================

#define N_TOK 8192
#define C_DIM 1024
#define H_DIM 2048
#define N_EXP 8
#define R_DIM 16

// ---------------- device scratch (allocation-free) -------------------------
__device__ float g_M8[N_EXP * C_DIM];
__device__ int   g_cnt[N_EXP];
__device__ int   g_off[N_EXP];
__device__ int   g_perm[N_EXP * N_TOK];
__device__ float g_score[N_TOK];
__device__ __nv_bfloat16 g_x_hi[(size_t)N_TOK * C_DIM];
__device__ __nv_bfloat16 g_x_lo[(size_t)N_TOK * C_DIM];
__device__ __nv_bfloat16 g_w1_hi[(size_t)N_EXP * H_DIM * C_DIM]; // [e][n][k]
__device__ __nv_bfloat16 g_w1_lo[(size_t)N_EXP * H_DIM * C_DIM];
__device__ __nv_bfloat16 g_w2_hi[(size_t)N_EXP * C_DIM * H_DIM];
__device__ __nv_bfloat16 g_w2_lo[(size_t)N_EXP * C_DIM * H_DIM];
__device__ __nv_bfloat16 g_h_hi[(size_t)N_TOK * H_DIM];
__device__ __nv_bfloat16 g_h_lo[(size_t)N_TOK * H_DIM];

// ---------------- low-level helpers ----------------------------------------
__device__ __forceinline__ uint32_t smem_u32_of(const void* p) {
    uint32_t a;
    asm("{ .reg .u64 t; cvta.to.shared.u64 t, %1; cvt.u32.u64 %0, t; }"
        : "=r"(a) : "l"(p));
    return a;
}
__device__ __forceinline__ void cp16(uint32_t saddr, const void* g) {
    asm volatile("cp.async.cg.shared.global [%0], [%1], 16;"
                 :: "r"(saddr), "l"(g));
}
#define CP_COMMIT() asm volatile("cp.async.commit_group;" ::: "memory")
#define CP_WAIT1()  asm volatile("cp.async.wait_group 1;" ::: "memory")

__device__ __forceinline__ void ldsm4(uint32_t* r, uint32_t addr) {
    asm volatile("ldmatrix.sync.aligned.m8n8.x4.shared.b16 {%0,%1,%2,%3}, [%4];"
                 : "=r"(r[0]), "=r"(r[1]), "=r"(r[2]), "=r"(r[3]) : "r"(addr));
}
__device__ __forceinline__ void mma_bf16(float* d, const uint32_t* a,
                                         uint32_t b0, uint32_t b1) {
    asm volatile(
        "mma.sync.aligned.m16n8k16.row.col.f32.bf16.bf16.f32 "
        "{%0,%1,%2,%3}, {%4,%5,%6,%7}, {%8,%9}, {%0,%1,%2,%3};"
        : "+f"(d[0]), "+f"(d[1]), "+f"(d[2]), "+f"(d[3])
        : "r"(a[0]), "r"(a[1]), "r"(a[2]), "r"(a[3]), "r"(b0), "r"(b1));
}
// smem tile layout: [128 rows][4 chunks of 16B], chunk' = chunk ^ ((row>>1)&3)
__device__ __forceinline__ uint32_t su(int row, int chunk) {
    return (uint32_t)(row * 64 + ((chunk ^ ((row >> 1) & 3)) << 4));
}

// ===========================================================================
// prep: fold gate weights; zero counters
// ===========================================================================
__global__ void prep_kernel(const float* __restrict__ Wr,
                            const float* __restrict__ wg) {
    int gid = blockIdx.x * blockDim.x + threadIdx.x;
    if (gid < N_EXP) g_cnt[gid] = 0;
    int e = gid >> 10;
    int c = gid & (C_DIM - 1);
    float s = 0.f;
#pragma unroll
    for (int j = 0; j < R_DIM; j++) { float v = wg[e * R_DIM + j]; s += v * v; }
    float inv = 1.f / fmaxf(sqrtf(s), 1e-4f);
    float acc = 0.f;
#pragma unroll
    for (int j = 0; j < R_DIM; j++)
        acc += wg[e * R_DIM + j] * inv * Wr[j * C_DIM + c];
    g_M8[e * C_DIM + c] = acc;
}

// ===========================================================================
// gate: one warp per token; top-1 expert + softmax score; bucket tokens
// ===========================================================================
__global__ __launch_bounds__(256) void gate_kernel(const float* __restrict__ x) {
    __shared__ float sM[N_EXP * C_DIM];
    for (int i = threadIdx.x; i < N_EXP * C_DIM; i += 256) sM[i] = g_M8[i];
    __syncthreads();
    int warp = threadIdx.x >> 5, lane = threadIdx.x & 31;
    int t = blockIdx.x * 8 + warp;
    const float* xr = x + (size_t)t * C_DIM;
    float acc[N_EXP];
#pragma unroll
    for (int e = 0; e < N_EXP; e++) acc[e] = 0.f;
    for (int k0 = 0; k0 < C_DIM; k0 += 32) {
        float xv = xr[k0 + lane];
#pragma unroll
        for (int e = 0; e < N_EXP; e++) acc[e] += xv * sM[e * C_DIM + k0 + lane];
    }
#pragma unroll
    for (int e = 0; e < N_EXP; e++)
#pragma unroll
        for (int off = 16; off > 0; off >>= 1)
            acc[e] += __shfl_xor_sync(0xffffffffu, acc[e], off);
    if (lane == 0) {
        float m = acc[0]; int idx = 0;
#pragma unroll
        for (int e = 1; e < N_EXP; e++) if (acc[e] > m) { m = acc[e]; idx = e; }
        float s = 0.f;
#pragma unroll
        for (int e = 0; e < N_EXP; e++) s += expf(acc[e] - m);
        g_score[t] = 1.0f / s;
        int pos = atomicAdd(&g_cnt[idx], 1);
        g_perm[idx * N_TOK + pos] = t;
    }
}

__global__ void scan_kernel() {
    int s = 0;
#pragma unroll
    for (int e = 0; e < N_EXP; e++) { g_off[e] = s; s += g_cnt[e]; }
}

// ===========================================================================
// split x -> bf16 hi/lo
// ===========================================================================
__global__ __launch_bounds__(256) void split_x_kernel(const float* __restrict__ x) {
    int i = blockIdx.x * 256 + threadIdx.x;
    float4 v = ((const float4*)x)[i];
    __nv_bfloat16 h[4], l[4];
    float vs[4] = {v.x, v.y, v.z, v.w};
#pragma unroll
    for (int j = 0; j < 4; j++) {
        h[j] = __float2bfloat16(vs[j]);
        l[j] = __float2bfloat16(vs[j] - __bfloat162float(h[j]));
    }
    ((uint2*)g_x_hi)[i] = *(uint2*)h;
    ((uint2*)g_x_lo)[i] = *(uint2*)l;
}

// ===========================================================================
// transpose + split weights: [e][KK][NN] fp32 -> [e][NN][KK] bf16 hi/lo
// ===========================================================================
template <int KK, int NN, bool IS_W1>
__global__ __launch_bounds__(256) void transpose_split_kernel(const float* __restrict__ W) {
    __nv_bfloat16* oh = IS_W1 ? g_w1_hi : g_w2_hi;
    __nv_bfloat16* ol = IS_W1 ? g_w1_lo : g_w2_lo;
    __shared__ float t[32][33];
    int e = blockIdx.z;
    int n0b = blockIdx.x * 32, k0b = blockIdx.y * 32;
    int tx = threadIdx.x, ty = threadIdx.y;
    const float* src = W + (size_t)e * KK * NN;
#pragma unroll
    for (int j = 0; j < 4; j++)
        t[ty + j * 8][tx] = src[(size_t)(k0b + ty + j * 8) * NN + n0b + tx];
    __syncthreads();
#pragma unroll
    for (int j = 0; j < 4; j++) {
        int n = n0b + ty + j * 8;
        int k = k0b + tx;
        float v = t[tx][ty + j * 8];
        __nv_bfloat16 hh = __float2bfloat16(v);
        size_t o = ((size_t)e * NN + n) * KK + k;
        oh[o] = hh;
        ol[o] = __float2bfloat16(v - __bfloat162float(hh));
    }
}

// ===========================================================================
// Grouped GEMM via mma.sync bf16 3-split.
// Tile BM=128, BN=128, BK=32, 128 threads (4 warps, warp tile 64x64), 3-stage
// cp.async pipeline, 32KB/stage (Ahi|Alo|Bhi|Blo 8KB each).
//   GELU=true : A = x(hi/lo) gathered via perm, B = W1t -> h(hi/lo) + gelu
//   GELU=false: A = h(hi/lo) contiguous,       B = W2t -> out f32 * score
// ===========================================================================
#define STAGE_BYTES 32768
#define NSTAGE 3

template <int KD, int ND, bool GELU>
__global__ __launch_bounds__(128)
void ffn_gemm_mma(const float* __restrict__ bias_all, float* __restrict__ out_ext) {
    const int e   = blockIdx.z;
    const int cnt = g_cnt[e];
    const int m0  = blockIdx.y * 128;
    if (m0 >= cnt) return;
    const int n0  = blockIdx.x * 128;
    const int off_e = g_off[e];

    extern __shared__ char smem[];
    const uint32_t sbase = smem_u32_of(smem);

    const int tid  = threadIdx.x;
    const int lane = tid & 31;
    const int wid  = tid >> 5;
    const int wm   = wid & 1;        // m-warp (64 rows)
    const int wn   = wid >> 1;       // n-warp (64 cols)

    const __nv_bfloat16* Ah = GELU ? g_x_hi : g_h_hi;
    const __nv_bfloat16* Al = GELU ? g_x_lo : g_h_lo;
    const __nv_bfloat16* Bh = GELU ? g_w1_hi : g_w2_hi;
    const __nv_bfloat16* Bl = GELU ? g_w1_lo : g_w2_lo;

    // ---- loader precompute: 4 chunks per thread per matrix ----
    uint32_t sdst[4];
    uint32_t asrc[4], bsrc[4];   // byte offsets
    {
        const int chunk = tid & 3;
#pragma unroll
        for (int i = 0; i < 4; i++) {
            int row = (tid >> 2) + i * 32;
            sdst[i] = su(row, chunk);
            int m = m0 + row;
            int mc = m < cnt ? m : cnt - 1;
            int arow = GELU ? g_perm[e * N_TOK + mc] : (off_e + mc);
            asrc[i] = (uint32_t)(((size_t)arow * KD + chunk * 8) * 2);
            bsrc[i] = (uint32_t)((((size_t)e * ND + n0 + row) * KD + chunk * 8) * 2);
        }
    }

    // ---- ldmatrix address precompute (k16=0, stage 0) ----
    uint32_t aaddr[4], baddr[4];
    {
        const int grp = lane >> 3;
#pragma unroll
        for (int tm = 0; tm < 4; tm++) {
            int row = wm * 64 + tm * 16 + (lane & 7) + (grp & 1) * 8;
            aaddr[tm] = sbase + su(row, grp >> 1);
        }
#pragma unroll
        for (int t16 = 0; t16 < 4; t16++) {
            int row = wn * 64 + t16 * 16 + (lane & 7) + (grp >> 1) * 8;
            baddr[t16] = sbase + 16384 + su(row, grp & 1);
        }
    }

    float acc[4][8][4];
#pragma unroll
    for (int i = 0; i < 4; i++)
#pragma unroll
        for (int j = 0; j < 8; j++)
#pragma unroll
            for (int q = 0; q < 4; q++) acc[i][j][q] = 0.f;

    constexpr int NC = KD / 32;

    // stage load: 16 cp.async x 16B per thread
    auto load_stage = [&](int s, int kt) {
        const uint32_t sb = sbase + s * STAGE_BYTES;
        const uint32_t ko = (uint32_t)(kt * 64);   // 32 bf16 = 64B
#pragma unroll
        for (int i = 0; i < 4; i++) {
            cp16(sb +         sdst[i], (const char*)Ah + asrc[i] + ko);
            cp16(sb + 8192  + sdst[i], (const char*)Al + asrc[i] + ko);
            cp16(sb + 16384 + sdst[i], (const char*)Bh + bsrc[i] + ko);
            cp16(sb + 24576 + sdst[i], (const char*)Bl + bsrc[i] + ko);
        }
    };

    load_stage(0, 0); CP_COMMIT();
    load_stage(1, 1); CP_COMMIT();

#pragma unroll 1
    for (int kt = 0; kt < NC; kt++) {
        CP_WAIT1();
        __syncthreads();
        const int s = kt % NSTAGE;
        const uint32_t soff = (uint32_t)(s * STAGE_BYTES);
#pragma unroll
        for (int k16 = 0; k16 < 2; k16++) {
            const uint32_t kx = (uint32_t)(k16 << 5);
            uint32_t ah[4][4], al[4][4], bh[4][4], bl[4][4];
#pragma unroll
            for (int tm = 0; tm < 4; tm++) {
                uint32_t a = (aaddr[tm] + soff) ^ kx;
                ldsm4(ah[tm], a);
                ldsm4(al[tm], a + 8192);
            }
#pragma unroll
            for (int t16 = 0; t16 < 4; t16++) {
                uint32_t b = (baddr[t16] + soff) ^ kx;
                ldsm4(bh[t16], b);
                ldsm4(bl[t16], b + 8192);
            }
#pragma unroll
            for (int tm = 0; tm < 4; tm++) {
#pragma unroll
                for (int t16 = 0; t16 < 4; t16++) {
                    float* d0 = acc[tm][2 * t16];
                    float* d1 = acc[tm][2 * t16 + 1];
                    mma_bf16(d0, ah[tm], bh[t16][0], bh[t16][1]);
                    mma_bf16(d0, ah[tm], bl[t16][0], bl[t16][1]);
                    mma_bf16(d0, al[tm], bh[t16][0], bh[t16][1]);
                    mma_bf16(d1, ah[tm], bh[t16][2], bh[t16][3]);
                    mma_bf16(d1, ah[tm], bl[t16][2], bl[t16][3]);
                    mma_bf16(d1, al[tm], bh[t16][2], bh[t16][3]);
                }
            }
        }
        __syncthreads();
        if (kt + 2 < NC) load_stage((kt + 2) % NSTAGE, kt + 2);
        CP_COMMIT();
    }

    // ---------------- epilogue ----------------
    const int g = lane >> 2, t4 = lane & 3;
    const float* bias = bias_all + (size_t)e * ND + n0;
#pragma unroll
    for (int tm = 0; tm < 4; tm++) {
#pragma unroll
        for (int half = 0; half < 2; half++) {
            int mloc = m0 + wm * 64 + tm * 16 + g + half * 8;
            if (mloc >= cnt) continue;
            if (GELU) {
                size_t rowb = (size_t)(off_e + mloc) * H_DIM;
#pragma unroll
                for (int tn8 = 0; tn8 < 8; tn8++) {
                    int col = wn * 64 + tn8 * 8 + 2 * t4;
                    float2 bv = *(const float2*)(bias + col);
                    float z0 = acc[tm][tn8][half * 2 + 0] + bv.x;
                    float z1 = acc[tm][tn8][half * 2 + 1] + bv.y;
                    float g0 = 0.5f * z0 * (1.0f + erff(z0 * 0.70710678118654752f));
                    float g1 = 0.5f * z1 * (1.0f + erff(z1 * 0.70710678118654752f));
                    __nv_bfloat16 h0 = __float2bfloat16(g0);
                    __nv_bfloat16 h1 = __float2bfloat16(g1);
                    __nv_bfloat16 l0 = __float2bfloat16(g0 - __bfloat162float(h0));
                    __nv_bfloat16 l1 = __float2bfloat16(g1 - __bfloat162float(h1));
                    __nv_bfloat162 hp, lp;
                    hp.x = h0; hp.y = h1; lp.x = l0; lp.y = l1;
                    *(__nv_bfloat162*)(g_h_hi + rowb + n0 + col) = hp;
                    *(__nv_bfloat162*)(g_h_lo + rowb + n0 + col) = lp;
                }
            } else {
                int tok = g_perm[e * N_TOK + mloc];
                float sc = g_score[tok];
                float* orow = out_ext + (size_t)tok * C_DIM + n0;
#pragma unroll
                for (int tn8 = 0; tn8 < 8; tn8++) {
                    int col = wn * 64 + tn8 * 8 + 2 * t4;
                    float2 bv = *(const float2*)(bias + col);
                    float2 ov;
                    ov.x = (acc[tm][tn8][half * 2 + 0] + bv.x) * sc;
                    ov.y = (acc[tm][tn8][half * 2 + 1] + bv.y) * sc;
                    *(float2*)(orow + col) = ov;
                }
            }
        }
    }
}

// ===========================================================================
extern "C" void kernel_launch(void* const* d_in, const int* in_sizes, int n_in,
                              void* d_out, int out_size) {
    const float* x  = (const float*)d_in[0];
    const float* Wr = (const float*)d_in[1];
    const float* wg = (const float*)d_in[2];
    const float* W1 = (const float*)d_in[3];
    const float* b1 = (const float*)d_in[4];
    const float* W2 = (const float*)d_in[5];
    const float* b2 = (const float*)d_in[6];
    float* out = (float*)d_out;

    static int smem_set = 0;
    if (!smem_set) {
        cudaFuncSetAttribute(ffn_gemm_mma<C_DIM, H_DIM, true>,
                             cudaFuncAttributeMaxDynamicSharedMemorySize,
                             NSTAGE * STAGE_BYTES);
        cudaFuncSetAttribute(ffn_gemm_mma<H_DIM, C_DIM, false>,
                             cudaFuncAttributeMaxDynamicSharedMemorySize,
                             NSTAGE * STAGE_BYTES);
        smem_set = 1;
    }

    prep_kernel<<<(N_EXP * C_DIM) / 256, 256>>>(Wr, wg);
    gate_kernel<<<N_TOK / 8, 256>>>(x);
    scan_kernel<<<1, 1>>>();
    split_x_kernel<<<(N_TOK * C_DIM / 4) / 256, 256>>>(x);
    transpose_split_kernel<C_DIM, H_DIM, true>
        <<<dim3(H_DIM / 32, C_DIM / 32, N_EXP), dim3(32, 8)>>>(W1);
    transpose_split_kernel<H_DIM, C_DIM, false>
        <<<dim3(C_DIM / 32, H_DIM / 32, N_EXP), dim3(32, 8)>>>(W2);

    dim3 g1(H_DIM / 128, N_TOK / 128, N_EXP);
    ffn_gemm_mma<C_DIM, H_DIM, true><<<g1, 128, NSTAGE * STAGE_BYTES>>>(b1, nullptr);
    dim3 g2(C_DIM / 128, N_TOK / 128, N_EXP);
    ffn_gemm_mma<H_DIM, C_DIM, false><<<g2, 128, NSTAGE * STAGE_BYTES>>>(b2, out);
}